// round 14
// baseline (speedup 1.0000x reference)
#include <cuda_runtime.h>
#include <cuda_bf16.h>
#include <cstdint>

// causal softmax(QK^T/sqrt(64)): q,k [48,2048,64] fp32 -> out [48,2048,2048] fp32
//
// R14 single-pass register-hold design:
// prep_all: q -> bf16 hi/lo A-fragment scratch (16-row groups), k -> bf16 hi/lo
//           swizzled 64-key tile images; zero per-(bh,qb) flags.
// sdp_sp:   one kernel, per-bh bid blocks of 512:
//   r in [0,272): WORK CTA (bh, qb, tile t): 3-split MMA once, exp once, hold
//     scores in regs; post partial row sums to fixed slot g_part[fidx][t][*];
//     flag++; spin until group complete; reduce partials (coalesced, smem);
//     normalize held regs; streaming stores.
//   r in [272,512): ZERO CTA: stream-zero one upper-triangle 64-col tile.
// Deadlock-free: (bh,qb) groups are bid-contiguous, <=32 CTAs each; in-order
// dispatch => earliest unfinished group always fully resident.

#define TT 2048
#define NBH 48

__device__ __align__(16) char g_qf[(size_t)NBH * 16 * 32768];  // [bh][qb]: hi 16KB | lo 16KB
__device__ __align__(16) char g_ki[(size_t)NBH * 32 * 16384];  // [bh][t64]: hi 8KB | lo 8KB
__device__ float g_part[NBH * 16 * 32 * 128];                  // [bh][qb][t64][row]
__device__ unsigned g_flag[NBH * 16];                          // tiles done per (bh,qb)

__device__ __forceinline__ uint32_t smem_u32(const void* p) {
    uint32_t a;
    asm("{ .reg .u64 t; cvta.to.shared.u64 t, %1; cvt.u32.u64 %0, t; }" : "=r"(a) : "l"(p));
    return a;
}
__device__ __forceinline__ void ldsm_x4(uint32_t r[4], uint32_t addr) {
    asm volatile("ldmatrix.sync.aligned.m8n8.x4.shared.b16 {%0,%1,%2,%3}, [%4];"
        : "=r"(r[0]), "=r"(r[1]), "=r"(r[2]), "=r"(r[3]) : "r"(addr));
}
__device__ __forceinline__ void mma16816(float c[4], const uint32_t a[4], const uint32_t b[2]) {
    asm volatile("mma.sync.aligned.m16n8k16.row.col.f32.bf16.bf16.f32 "
        "{%0,%1,%2,%3}, {%4,%5,%6,%7}, {%8,%9}, {%0,%1,%2,%3};"
        : "+f"(c[0]), "+f"(c[1]), "+f"(c[2]), "+f"(c[3])
        : "r"(a[0]), "r"(a[1]), "r"(a[2]), "r"(a[3]), "r"(b[0]), "r"(b[1]));
}
#define CP_ASYNC16(sa, gp) \
    asm volatile("cp.async.cg.shared.global [%0], [%1], 16;" :: "r"(sa), "l"(gp))
#define CP_COMMIT() asm volatile("cp.async.commit_group;")
#define CP_WAIT0()  asm volatile("cp.async.wait_group 0;")

__device__ __forceinline__ void split2(float x, float y, uint32_t& h, uint32_t& l) {
    __nv_bfloat16 hx = __float2bfloat16(x);
    __nv_bfloat16 hy = __float2bfloat16(y);
    __nv_bfloat162 hv; hv.x = hx; hv.y = hy;
    __nv_bfloat162 lv;
    lv.x = __float2bfloat16(x - __bfloat162float(hx));
    lv.y = __float2bfloat16(y - __bfloat162float(hy));
    h = *reinterpret_cast<uint32_t*>(&hv);
    l = *reinterpret_cast<uint32_t*>(&lv);
}

// ---------------- prep_all: q-frag prep [0,768) | k tile prep [768,2304) ----------------
__global__ void __launch_bounds__(128)
prep_all(const float* __restrict__ qg, const float* __restrict__ kg)
{
    __shared__ __align__(16) char sm[32768];
    const int tid = threadIdx.x, w = tid >> 5, lane = tid & 31;
    int bid = (int)blockIdx.x;

    if (bid < 768) {
        const int qb = bid & 15, bh = bid >> 4;
        if (tid == 0) g_flag[(bh << 4) + qb] = 0u;

        const float* qptr = qg + ((size_t)bh * TT + (qb << 7)) * 64;
        #pragma unroll
        for (int i = 0; i < 8; i++) {
            const int idx = tid + (i << 7);
            const int r = idx >> 3, c = idx & 7;
            const float* p = qptr + r * 64 + (c << 3);
            float4 v0 = *(const float4*)p;
            float4 v1 = *(const float4*)(p + 4);
            v0.x *= 0.125f; v0.y *= 0.125f; v0.z *= 0.125f; v0.w *= 0.125f;
            v1.x *= 0.125f; v1.y *= 0.125f; v1.z *= 0.125f; v1.w *= 0.125f;
            uint4 h, l;
            split2(v0.x, v0.y, h.x, l.x);
            split2(v0.z, v0.w, h.y, l.y);
            split2(v1.x, v1.y, h.z, l.z);
            split2(v1.z, v1.w, h.w, l.w);
            const uint32_t off = (r << 7) + (((uint32_t)c ^ (r & 7)) << 4);
            *(uint4*)(sm + off) = h;
            *(uint4*)(sm + 16384 + off) = l;
        }
        __syncthreads();

        const uint32_t sb = smem_u32(sm);
        // extract A fragments for 16-row groups g = 2w, 2w+1
        const int cpar = lane >> 4;
        char* dst = g_qf + ((size_t)((bh << 4) + qb) << 15);
        #pragma unroll
        for (int r2 = 0; r2 < 2; r2++) {
            const int g = (w << 1) + r2;
            const int rA = (g << 4) + (lane & 15);
            #pragma unroll
            for (int kc = 0; kc < 4; kc++) {
                const uint32_t off = (uint32_t)(rA << 7)
                                   + (((uint32_t)((kc << 1) + cpar) ^ (rA & 7)) << 4);
                uint32_t h[4], l[4];
                ldsm_x4(h, sb + off);
                ldsm_x4(l, sb + 16384 + off);
                const uint32_t a = (uint32_t)(((((g << 2) + kc) << 5) + lane) << 4);
                *(uint4*)(dst + a)         = make_uint4(h[0], h[1], h[2], h[3]);
                *(uint4*)(dst + 16384 + a) = make_uint4(l[0], l[1], l[2], l[3]);
            }
        }
        return;
    }

    // ---- k prep: 1536 CTAs x 512 chunks/CTA ----
    bid -= 768;
    #pragma unroll
    for (int j = 0; j < 4; j++) {
        const int idx = (bid << 9) + (j << 7) + tid;
        const int kgr = idx >> 3;
        const int c   = idx & 7;
        const float* p = kg + (size_t)kgr * 64 + (c << 3);
        const float4 v0 = *(const float4*)p;
        const float4 v1 = *(const float4*)(p + 4);
        uint4 h, l;
        split2(v0.x, v0.y, h.x, l.x);
        split2(v0.z, v0.w, h.y, l.y);
        split2(v1.x, v1.y, h.z, l.z);
        split2(v1.z, v1.w, h.w, l.w);
        const uint32_t t64 = (uint32_t)kgr >> 6;
        const uint32_t row = (uint32_t)kgr & 63;
        const size_t off = ((size_t)t64 << 14) + row * 128 + (((uint32_t)c ^ (row & 7)) << 4);
        *(uint4*)(g_ki + off) = h;
        *(uint4*)(g_ki + off + 8192) = l;
    }
}

// ---------------- single-pass kernel ----------------
__global__ void __launch_bounds__(256, 2)
sdp_sp(float* __restrict__ outg)
{
    __shared__ __align__(16) char smK[16384];
    __shared__ float s_inv[128];

    const int tid  = threadIdx.x;
    const int w    = tid >> 5;          // 0..7, warp = 16 rows
    const int lane = tid & 31;
    const int bh   = (int)blockIdx.x >> 9;
    const int r    = (int)blockIdx.x & 511;
    float* outp = outg + (size_t)bh * TT * TT;

    if (r >= 272) {
        // ---------------- ZERO CTA ----------------
        int r2 = r - 272;                       // [0,240)
        int qb = 0;
        while (r2 >= 30 - 2 * qb) { r2 -= 30 - 2 * qb; qb++; }
        const int zt = 2 * qb + 2 + r2;         // tile64 index
        const int q0 = qb << 7;
        const float4 z4 = make_float4(0.f, 0.f, 0.f, 0.f);
        #pragma unroll
        for (int i = 0; i < 8; i++) {
            const int idx = tid + (i << 8);     // 0..2047 float4
            const int rr = idx >> 4, c4 = (idx & 15) << 2;
            __stcs((float4*)(outp + (size_t)(q0 + rr) * TT + (zt << 6) + c4), z4);
        }
        return;
    }

    // ---------------- WORK CTA ----------------
    int qp = 0;
    while ((qp + 1) * (33 - (qp + 1)) <= r) qp++;   // group index (heavy first)
    const int qb = 15 - qp;
    const int t  = r - qp * (33 - qp);              // tile64 0..2qb+1
    const int q0 = qb << 7;
    const int ntiles = 2 * qb + 2;
    const int fidx = (bh << 4) + qb;
    const bool msk = (t >= 2 * qb);

    // K tile copy (16KB: hi 8KB || lo 8KB)
    const char* kb = g_ki + ((size_t)(bh * 32 + t) << 14);
    {
        const uint32_t sb = smem_u32(smK);
        #pragma unroll
        for (int i = 0; i < 4; i++)
            CP_ASYNC16(sb + (uint32_t)tid * 16 + (i << 12), kb + tid * 16 + (i << 12));
        CP_COMMIT();
    }

    // A fragments for 16-row group g = w
    uint32_t ah[4][4], al[4][4];
    {
        const char* src = g_qf + ((size_t)fidx << 15);
        #pragma unroll
        for (int kc = 0; kc < 4; kc++) {
            const uint32_t a = (uint32_t)(((((w << 2) + kc) << 5) + lane) << 4);
            const uint4 h = *(const uint4*)(src + a);
            ah[kc][0] = h.x; ah[kc][1] = h.y; ah[kc][2] = h.z; ah[kc][3] = h.w;
            const uint4 l = *(const uint4*)(src + 16384 + a);
            al[kc][0] = l.x; al[kc][1] = l.y; al[kc][2] = l.z; al[kc][3] = l.w;
        }
    }

    const int rowB  = (lane & 7) + ((lane >> 4) << 3);
    const int cparB = (lane >> 3) & 1;
    uint32_t bOff[4];
    #pragma unroll
    for (int kc = 0; kc < 4; kc++)
        bOff[kc] = (uint32_t)(rowB << 7)
                 + (((uint32_t)((kc << 1) + cparB) ^ (rowB & 7)) << 4);

    const int lrow  = (w << 4) + (lane >> 2);       // local row (lo); hi = +8
    const int grow0 = q0 + lrow;
    const int grow1 = grow0 + 8;
    const int cbase = (lane & 3) << 1;

    CP_WAIT0();
    __syncthreads();
    const uint32_t sb = smem_u32(smK);

    // ---- 3-split MMA over the 64-key tile; exp in place; partial sums ----
    float sc[4][8];                                  // [nfp][a0[4]|a1[4]]
    float s0 = 0.f, s1 = 0.f;
    #pragma unroll
    for (int nfp = 0; nfp < 4; nfp++) {
        float a0[4] = {0,0,0,0}, a1[4] = {0,0,0,0};
        const uint32_t nbase = sb + ((uint32_t)nfp << 11);
        #pragma unroll
        for (int kc = 0; kc < 4; kc++) {
            uint32_t bhr[4], blr[4];
            ldsm_x4(bhr, nbase + bOff[kc]);
            ldsm_x4(blr, nbase + 8192 + bOff[kc]);
            mma16816(a0, ah[kc], &bhr[0]);
            mma16816(a1, ah[kc], &bhr[2]);
            mma16816(a0, ah[kc], &blr[0]);
            mma16816(a1, ah[kc], &blr[2]);
            mma16816(a0, al[kc], &bhr[0]);
            mma16816(a1, al[kc], &bhr[2]);
        }
        const int c0 = (t << 6) + (nfp << 4) + cbase;
        if (!msk) {
            a0[0] = __expf(a0[0]); a0[1] = __expf(a0[1]);
            a0[2] = __expf(a0[2]); a0[3] = __expf(a0[3]);
            a1[0] = __expf(a1[0]); a1[1] = __expf(a1[1]);
            a1[2] = __expf(a1[2]); a1[3] = __expf(a1[3]);
        } else {
            a0[0] = (c0     <= grow0) ? __expf(a0[0]) : 0.f;
            a0[1] = (c0 + 1 <= grow0) ? __expf(a0[1]) : 0.f;
            a0[2] = (c0     <= grow1) ? __expf(a0[2]) : 0.f;
            a0[3] = (c0 + 1 <= grow1) ? __expf(a0[3]) : 0.f;
            a1[0] = (c0 + 8 <= grow0) ? __expf(a1[0]) : 0.f;
            a1[1] = (c0 + 9 <= grow0) ? __expf(a1[1]) : 0.f;
            a1[2] = (c0 + 8 <= grow1) ? __expf(a1[2]) : 0.f;
            a1[3] = (c0 + 9 <= grow1) ? __expf(a1[3]) : 0.f;
        }
        s0 += (a0[0] + a0[1]) + (a1[0] + a1[1]);
        s1 += (a0[2] + a0[3]) + (a1[2] + a1[3]);
        #pragma unroll
        for (int j = 0; j < 4; j++) { sc[nfp][j] = a0[j]; sc[nfp][4 + j] = a1[j]; }
    }

    // reduce across the 4 lanes sharing each row; post fixed partial slot
    s0 += __shfl_xor_sync(0xffffffffu, s0, 1);
    s0 += __shfl_xor_sync(0xffffffffu, s0, 2);
    s1 += __shfl_xor_sync(0xffffffffu, s1, 1);
    s1 += __shfl_xor_sync(0xffffffffu, s1, 2);
    float* pslot = g_part + ((size_t)(fidx * 32 + t) << 7);
    if ((lane & 3) == 0) {
        pslot[lrow]     = s0;
        pslot[lrow + 8] = s1;
    }
    __threadfence();
    __syncthreads();
    if (tid == 0) {
        atomicAdd(&g_flag[fidx], 1u);
        // spin until the whole (bh,qb) group has posted
        unsigned v;
        do {
            asm volatile("ld.acquire.gpu.global.b32 %0, [%1];"
                         : "=r"(v) : "l"(&g_flag[fidx]) : "memory");
            if ((int)v >= ntiles) break;
            __nanosleep(64);
        } while (true);
    }
    __syncthreads();

    // ---- combine partials (coalesced: thread=row), publish inv via smem ----
    if (tid < 128) {
        const float* pbase = g_part + ((size_t)fidx << 12);   // fidx*32*128
        float s = 0.f;
        for (int tt = 0; tt < ntiles; tt++)
            s += pbase[(tt << 7) + tid];
        s_inv[tid] = 1.0f / s;
    }
    __syncthreads();
    const float inv0 = s_inv[lrow];
    const float inv1 = s_inv[lrow + 8];

    // ---- normalize held registers, streaming stores ----
    float* or0 = outp + (size_t)grow0 * TT;
    float* or1 = outp + (size_t)grow1 * TT;
    #pragma unroll
    for (int nfp = 0; nfp < 4; nfp++) {
        const int c0 = (t << 6) + (nfp << 4) + cbase;
        float2 v;
        v.x = sc[nfp][0] * inv0; v.y = sc[nfp][1] * inv0;
        __stcs((float2*)(or0 + c0), v);
        v.x = sc[nfp][4] * inv0; v.y = sc[nfp][5] * inv0;
        __stcs((float2*)(or0 + c0 + 8), v);
        v.x = sc[nfp][2] * inv1; v.y = sc[nfp][3] * inv1;
        __stcs((float2*)(or1 + c0), v);
        v.x = sc[nfp][6] * inv1; v.y = sc[nfp][7] * inv1;
        __stcs((float2*)(or1 + c0 + 8), v);
    }
}

extern "C" void kernel_launch(void* const* d_in, const int* in_sizes, int n_in,
                              void* d_out, int out_size)
{
    const float* q = (const float*)d_in[0];
    const float* k = (const float*)d_in[1];
    float* out = (float*)d_out;

    // prep: [0,768) q-frag prep (+flag reset), [768,2304) k tile prep
    prep_all<<<2304, 128>>>(q, k);

    // per-bh blocks of 512 bids: [0,272) work (heavy qb first), [272,512) zero-fill
    sdp_sp<<<NBH * 512, 256>>>(out);
}

// round 15
// speedup vs baseline: 1.5606x; 1.5606x over previous
#include <cuda_runtime.h>
#include <cuda_bf16.h>
#include <cstdint>

// causal softmax(QK^T/sqrt(64)): q,k [48,2048,64] fp32 -> out [48,2048,2048] fp32
//
// prep_all (ONE launch, bid-split):
//   [0,768)    q -> bf16 hi/lo A-FRAGMENT-layout scratch; zero partials+flags
//   [768,2304) k -> bf16 hi/lo swizzled smem-image tile scratch
// sdp_fused: phase INTERLEAVED per bh: z even = sum CTAs of bh=z/2, z odd =
//   store CTAs of bh=z/2 -> resident mix is ~50/50 sum/store the whole kernel
//   (sum: MUFU + zero-fill writes; store: tensor + output stores), and stores
//   hit the same bh's K tiles while L2-hot.
//   sum: MMA (1-split bf16 qb>=1 / 3-split qb==0) + exp -> partial row sums;
//        post flag (release); upper-triangle zero-fill (streaming stores).
//   store: prefetch K + A frags, spin (acquire) on flag, 3-split MMA, exp,
//        normalize, streaming stores.
// Deadlock-free: producers have strictly lower bids and never wait.

#define TT 2048
#define NBH 48

__device__ __align__(16) char g_qf[(size_t)NBH * 16 * 32768];  // [bh][qb]: hi 16KB | lo 16KB
__device__ __align__(16) char g_ki[(size_t)NBH * 32 * 16384];  // [bh][t64]: hi 8KB | lo 8KB
__device__ float g_part[NBH * 16 * 4 * 128];                   // [bh][qb][chunk][row]
__device__ unsigned g_flag[NBH * 16];                          // completed chunks per (bh,qb)

#define SMEM_BYTES (3 * 16384)

__device__ __forceinline__ uint32_t smem_u32(const void* p) {
    uint32_t a;
    asm("{ .reg .u64 t; cvta.to.shared.u64 t, %1; cvt.u32.u64 %0, t; }" : "=r"(a) : "l"(p));
    return a;
}
__device__ __forceinline__ void ldsm_x4(uint32_t r[4], uint32_t addr) {
    asm volatile("ldmatrix.sync.aligned.m8n8.x4.shared.b16 {%0,%1,%2,%3}, [%4];"
        : "=r"(r[0]), "=r"(r[1]), "=r"(r[2]), "=r"(r[3]) : "r"(addr));
}
__device__ __forceinline__ void mma16816(float c[4], const uint32_t a[4], const uint32_t b[2]) {
    asm volatile("mma.sync.aligned.m16n8k16.row.col.f32.bf16.bf16.f32 "
        "{%0,%1,%2,%3}, {%4,%5,%6,%7}, {%8,%9}, {%0,%1,%2,%3};"
        : "+f"(c[0]), "+f"(c[1]), "+f"(c[2]), "+f"(c[3])
        : "r"(a[0]), "r"(a[1]), "r"(a[2]), "r"(a[3]), "r"(b[0]), "r"(b[1]));
}
#define CP_ASYNC16(sa, gp) \
    asm volatile("cp.async.cg.shared.global [%0], [%1], 16;" :: "r"(sa), "l"(gp))
#define CP_COMMIT() asm volatile("cp.async.commit_group;")
#define CP_WAIT2()  asm volatile("cp.async.wait_group 2;")

__device__ __forceinline__ void split2(float x, float y, uint32_t& h, uint32_t& l) {
    __nv_bfloat16 hx = __float2bfloat16(x);
    __nv_bfloat16 hy = __float2bfloat16(y);
    __nv_bfloat162 hv; hv.x = hx; hv.y = hy;
    __nv_bfloat162 lv;
    lv.x = __float2bfloat16(x - __bfloat162float(hx));
    lv.y = __float2bfloat16(y - __bfloat162float(hy));
    h = *reinterpret_cast<uint32_t*>(&hv);
    l = *reinterpret_cast<uint32_t*>(&lv);
}

// ---------------- prep_all: q-frag prep [0,768) | k tile prep [768,2304) ----------------
__global__ void __launch_bounds__(128)
prep_all(const float* __restrict__ qg, const float* __restrict__ kg)
{
    __shared__ __align__(16) char sm[32768];
    const int tid = threadIdx.x, w = tid >> 5, lane = tid & 31;
    int bid = (int)blockIdx.x;

    if (bid < 768) {
        const int qb = bid & 15, bh = bid >> 4;
        {
            const int base = ((bh << 4) + qb) << 9;
            #pragma unroll
            for (int j = 0; j < 4; j++) g_part[base + (j << 7) + tid] = 0.0f;
            if (tid == 0) g_flag[(bh << 4) + qb] = 0u;
        }

        const float* qptr = qg + ((size_t)bh * TT + (qb << 7)) * 64;
        #pragma unroll
        for (int i = 0; i < 8; i++) {
            const int idx = tid + (i << 7);
            const int r = idx >> 3, c = idx & 7;
            const float* p = qptr + r * 64 + (c << 3);
            float4 v0 = *(const float4*)p;
            float4 v1 = *(const float4*)(p + 4);
            v0.x *= 0.125f; v0.y *= 0.125f; v0.z *= 0.125f; v0.w *= 0.125f;
            v1.x *= 0.125f; v1.y *= 0.125f; v1.z *= 0.125f; v1.w *= 0.125f;
            uint4 h, l;
            split2(v0.x, v0.y, h.x, l.x);
            split2(v0.z, v0.w, h.y, l.y);
            split2(v1.x, v1.y, h.z, l.z);
            split2(v1.z, v1.w, h.w, l.w);
            const uint32_t off = (r << 7) + (((uint32_t)c ^ (r & 7)) << 4);
            *(uint4*)(sm + off) = h;
            *(uint4*)(sm + 16384 + off) = l;
        }
        __syncthreads();

        const uint32_t sb = smem_u32(sm);
        uint32_t ah[2][4][4], al[2][4][4];
        const int cpar = lane >> 4;
        #pragma unroll
        for (int r2 = 0; r2 < 2; r2++) {
            const int rA = (w << 5) + (r2 << 4) + (lane & 15);
            #pragma unroll
            for (int kc = 0; kc < 4; kc++) {
                const uint32_t off = (uint32_t)(rA << 7)
                                   + (((uint32_t)((kc << 1) + cpar) ^ (rA & 7)) << 4);
                ldsm_x4(ah[r2][kc], sb + off);
                ldsm_x4(al[r2][kc], sb + 16384 + off);
            }
        }
        char* dst = g_qf + ((size_t)((bh << 4) + qb) << 15);
        #pragma unroll
        for (int r2 = 0; r2 < 2; r2++) {
            const int g = (w << 1) + r2;
            #pragma unroll
            for (int kc = 0; kc < 4; kc++) {
                const uint32_t a = (uint32_t)(((((g << 2) + kc) << 5) + lane) << 4);
                *(uint4*)(dst + a) =
                    make_uint4(ah[r2][kc][0], ah[r2][kc][1], ah[r2][kc][2], ah[r2][kc][3]);
                *(uint4*)(dst + 16384 + a) =
                    make_uint4(al[r2][kc][0], al[r2][kc][1], al[r2][kc][2], al[r2][kc][3]);
            }
        }
        return;
    }

    // ---- k prep: 1536 CTAs x 512 chunks/CTA covers 786432 chunks ----
    bid -= 768;
    #pragma unroll
    for (int j = 0; j < 4; j++) {
        const int idx = (bid << 9) + (j << 7) + tid;
        const int kgr = idx >> 3;
        const int c   = idx & 7;
        const float* p = kg + (size_t)kgr * 64 + (c << 3);
        const float4 v0 = *(const float4*)p;
        const float4 v1 = *(const float4*)(p + 4);
        uint4 h, l;
        split2(v0.x, v0.y, h.x, l.x);
        split2(v0.z, v0.w, h.y, l.y);
        split2(v1.x, v1.y, h.z, l.z);
        split2(v1.z, v1.w, h.w, l.w);
        const uint32_t t64 = (uint32_t)kgr >> 6;
        const uint32_t row = (uint32_t)kgr & 63;
        const size_t off = ((size_t)t64 << 14) + row * 128 + (((uint32_t)c ^ (row & 7)) << 4);
        *(uint4*)(g_ki + off) = h;
        *(uint4*)(g_ki + off + 8192) = l;
    }
}

// ---------------- shared machinery ----------------
__device__ __forceinline__ void load_afrags(const char* src, int w, int lane, bool with_lo,
                                            uint32_t ah[2][4][4], uint32_t al[2][4][4])
{
    #pragma unroll
    for (int r2 = 0; r2 < 2; r2++) {
        const int g = (w << 1) + r2;
        #pragma unroll
        for (int kc = 0; kc < 4; kc++) {
            const uint32_t a = (uint32_t)(((((g << 2) + kc) << 5) + lane) << 4);
            const uint4 h = *(const uint4*)(src + a);
            ah[r2][kc][0] = h.x; ah[r2][kc][1] = h.y; ah[r2][kc][2] = h.z; ah[r2][kc][3] = h.w;
            if (with_lo) {
                const uint4 l = *(const uint4*)(src + 16384 + a);
                al[r2][kc][0] = l.x; al[r2][kc][1] = l.y; al[r2][kc][2] = l.z; al[r2][kc][3] = l.w;
            }
        }
    }
}

__device__ __forceinline__ void issue_tile(uint32_t sb, int stage, const char* src,
                                           int tid, bool with_lo)
{
    const uint32_t dst = sb + ((uint32_t)stage << 14) + ((uint32_t)tid << 4);
    const char* s = src + (tid << 4);
    #pragma unroll
    for (int i = 0; i < 4; i++)
        CP_ASYNC16(dst + (i << 11), s + (i << 11));
    if (with_lo) {
        #pragma unroll
        for (int i = 4; i < 8; i++)
            CP_ASYNC16(dst + (i << 11), s + (i << 11));
    }
}

__device__ __forceinline__ void mma_tile3(uint32_t nbase, const uint32_t bOff[4],
                                          const uint32_t ah[2][4][4], const uint32_t al[2][4][4],
                                          float a00[4], float a01[4], float a10[4], float a11[4])
{
    #pragma unroll
    for (int kc = 0; kc < 4; kc++) {
        uint32_t bhr[4], blr[4];
        ldsm_x4(bhr, nbase + bOff[kc]);
        ldsm_x4(blr, nbase + 8192 + bOff[kc]);
        mma16816(a00, ah[0][kc], &bhr[0]);
        mma16816(a01, ah[0][kc], &bhr[2]);
        mma16816(a10, ah[1][kc], &bhr[0]);
        mma16816(a11, ah[1][kc], &bhr[2]);
        mma16816(a00, ah[0][kc], &blr[0]);
        mma16816(a01, ah[0][kc], &blr[2]);
        mma16816(a10, ah[1][kc], &blr[0]);
        mma16816(a11, ah[1][kc], &blr[2]);
        mma16816(a00, al[0][kc], &bhr[0]);
        mma16816(a01, al[0][kc], &bhr[2]);
        mma16816(a10, al[1][kc], &bhr[0]);
        mma16816(a11, al[1][kc], &bhr[2]);
    }
}

__device__ __forceinline__ void mma_tile1(uint32_t nbase, const uint32_t bOff[4],
                                          const uint32_t ah[2][4][4],
                                          float a00[4], float a01[4], float a10[4], float a11[4])
{
    #pragma unroll
    for (int kc = 0; kc < 4; kc++) {
        uint32_t bhr[4];
        ldsm_x4(bhr, nbase + bOff[kc]);
        mma16816(a00, ah[0][kc], &bhr[0]);
        mma16816(a01, ah[0][kc], &bhr[2]);
        mma16816(a10, ah[1][kc], &bhr[0]);
        mma16816(a11, ah[1][kc], &bhr[2]);
    }
}

// ---------------- fused sum+store kernel (per-bh interleaved phases) ----------------
__global__ void __launch_bounds__(128, 4)
sdp_fused(float* __restrict__ outg)
{
    extern __shared__ char smem[];
    const uint32_t sb = smem_u32(smem);
    const int tid = threadIdx.x, w = tid >> 5, lane = tid & 31;
    const int ch = blockIdx.x;
    const int qb = 15 - (int)blockIdx.y;
    const int bh = (int)blockIdx.z >> 1;          // per-bh interleave
    const bool is_store = (blockIdx.z & 1);       // even=sum, odd=store
    const int t_lo = ch << 3;
    const int dlim = 2 * qb + 1;
    const int q0 = qb << 7;
    const int nchunks = (dlim >> 3) + 1;
    const int fidx = (bh << 4) + qb;
    float* outp = outg + (size_t)bh * TT * TT;

    if (is_store && t_lo > dlim) return;

    const bool has_mma = (t_lo <= dlim);
    const int t_hi = min(t_lo + 7, dlim);
    const int nm = has_mma ? (t_hi - t_lo + 1) : 0;
    const bool full = is_store || (qb == 0);

    uint32_t ah[2][4][4], al[2][4][4];
    const int rowB  = (lane & 7) + ((lane >> 4) << 3);
    const int cparB = (lane >> 3) & 1;
    uint32_t bOff[4];
    #pragma unroll
    for (int kc = 0; kc < 4; kc++)
        bOff[kc] = (uint32_t)(rowB << 7)
                 + (((uint32_t)((kc << 1) + cparB) ^ (rowB & 7)) << 4);
    const int cbase = (lane & 3) << 1;
    int lr[2], grow0[2], grow1[2];
    #pragma unroll
    for (int r2 = 0; r2 < 2; r2++) {
        lr[r2] = (w << 5) + (r2 << 4) + (lane >> 2);
        grow0[r2] = q0 + lr[r2];
        grow1[r2] = grow0[r2] + 8;
    }

    const char* kb = g_ki + ((size_t)(bh * 32 + t_lo) << 14);

    if (has_mma) {
        load_afrags(g_qf + ((size_t)fidx << 15), w, lane, full, ah, al);
        #pragma unroll
        for (int p = 0; p < 3; p++) {
            if (p < nm) issue_tile(sb, p, kb + ((size_t)p << 14), tid, full);
            CP_COMMIT();
        }
    }

    if (!is_store) {
        // =================== SUM PHASE ===================
        if (has_mma) {
            float s0[2] = {0.f, 0.f}, s1[2] = {0.f, 0.f};
            #pragma unroll 1
            for (int i = 0; i < nm; i++) {
                CP_WAIT2();
                __syncthreads();
                const uint32_t stg = sb + ((uint32_t)(i % 3) << 14);
                const int tg = t_lo + i;
                const bool msk = (tg >= 2 * qb);
                #pragma unroll 1
                for (int nfp = 0; nfp < 4; nfp++) {
                    float a00[4] = {0,0,0,0}, a01[4] = {0,0,0,0};
                    float a10[4] = {0,0,0,0}, a11[4] = {0,0,0,0};
                    const uint32_t nbase = stg + ((uint32_t)nfp << 11);
                    if (full) mma_tile3(nbase, bOff, ah, al, a00, a01, a10, a11);
                    else      mma_tile1(nbase, bOff, ah,     a00, a01, a10, a11);

                    const int c0 = (tg << 6) + (nfp << 4) + cbase;
                    #pragma unroll
                    for (int r2 = 0; r2 < 2; r2++) {
                        float* accA = r2 ? a10 : a00;
                        float* accB = r2 ? a11 : a01;
                        if (!msk) {
                            s0[r2] += __expf(accA[0]) + __expf(accA[1])
                                    + __expf(accB[0]) + __expf(accB[1]);
                            s1[r2] += __expf(accA[2]) + __expf(accA[3])
                                    + __expf(accB[2]) + __expf(accB[3]);
                        } else {
                            if (c0     <= grow0[r2]) s0[r2] += __expf(accA[0]);
                            if (c0 + 1 <= grow0[r2]) s0[r2] += __expf(accA[1]);
                            if (c0 + 8 <= grow0[r2]) s0[r2] += __expf(accB[0]);
                            if (c0 + 9 <= grow0[r2]) s0[r2] += __expf(accB[1]);
                            if (c0     <= grow1[r2]) s1[r2] += __expf(accA[2]);
                            if (c0 + 1 <= grow1[r2]) s1[r2] += __expf(accA[3]);
                            if (c0 + 8 <= grow1[r2]) s1[r2] += __expf(accB[2]);
                            if (c0 + 9 <= grow1[r2]) s1[r2] += __expf(accB[3]);
                        }
                    }
                }
                __syncthreads();
                if (i + 3 < nm) issue_tile(sb, (i + 3) % 3, kb + ((size_t)(i + 3) << 14), tid, full);
                CP_COMMIT();
            }

            #pragma unroll
            for (int r2 = 0; r2 < 2; r2++) {
                s0[r2] += __shfl_xor_sync(0xffffffffu, s0[r2], 1);
                s0[r2] += __shfl_xor_sync(0xffffffffu, s0[r2], 2);
                s1[r2] += __shfl_xor_sync(0xffffffffu, s1[r2], 1);
                s1[r2] += __shfl_xor_sync(0xffffffffu, s1[r2], 2);
            }
            if ((lane & 3) == 0) {
                float* pp = g_part + (size_t)(((fidx << 2) + ch) << 7);
                #pragma unroll
                for (int r2 = 0; r2 < 2; r2++) {
                    pp[lr[r2]]     = s0[r2];
                    pp[lr[r2] + 8] = s1[r2];
                }
            }
            __threadfence();
            __syncthreads();
            if (tid == 0) atomicAdd(&g_flag[fidx], 1u);
        }

        // zero-fill tiles of this chunk above the diagonal band (streaming stores)
        const int z_lo = max(t_lo, 2 * qb + 2);
        const float4 z4 = make_float4(0.f, 0.f, 0.f, 0.f);
        for (int tg = z_lo; tg <= t_lo + 7; tg++) {
            #pragma unroll
            for (int i = 0; i < 16; i++) {
                const int idx = tid + (i << 7);
                const int rr = idx >> 4, c4 = idx & 15;
                __stcs((float4*)(outp + (size_t)(q0 + rr) * TT + (tg << 6) + (c4 << 2)), z4);
            }
        }
        return;
    }

    // =================== STORE PHASE ===================
    if (tid == 0) {
        unsigned v;
        do {
            asm volatile("ld.acquire.gpu.global.b32 %0, [%1];"
                         : "=r"(v) : "l"(&g_flag[fidx]) : "memory");
            if ((int)v >= nchunks) break;
            __nanosleep(128);
        } while (true);
    }
    __syncthreads();

    float inv0[2], inv1[2];
    float* or0[2]; float* or1[2];
    const float* pp = g_part + ((size_t)fidx << 9);
    #pragma unroll
    for (int r2 = 0; r2 < 2; r2++) {
        const int ra = lr[r2], rb = lr[r2] + 8;
        inv0[r2] = 1.0f / (pp[ra] + pp[128 + ra] + pp[256 + ra] + pp[384 + ra]);
        inv1[r2] = 1.0f / (pp[rb] + pp[128 + rb] + pp[256 + rb] + pp[384 + rb]);
        or0[r2] = outp + (size_t)grow0[r2] * TT;
        or1[r2] = outp + (size_t)grow1[r2] * TT;
    }

    #pragma unroll 1
    for (int i = 0; i < nm; i++) {
        CP_WAIT2();
        __syncthreads();
        const uint32_t stg = sb + ((uint32_t)(i % 3) << 14);
        const int tg = t_lo + i;
        const bool msk = (tg >= 2 * qb);
        #pragma unroll 1
        for (int nfp = 0; nfp < 4; nfp++) {
            float a00[4] = {0,0,0,0}, a01[4] = {0,0,0,0};
            float a10[4] = {0,0,0,0}, a11[4] = {0,0,0,0};
            const uint32_t nbase = stg + ((uint32_t)nfp << 11);
            mma_tile3(nbase, bOff, ah, al, a00, a01, a10, a11);

            const int c0 = (tg << 6) + (nfp << 4) + cbase;
            #pragma unroll
            for (int r2 = 0; r2 < 2; r2++) {
                float* accA = r2 ? a10 : a00;
                float* accB = r2 ? a11 : a01;
                float2 v;
                if (!msk) {
                    v.x = __expf(accA[0]) * inv0[r2]; v.y = __expf(accA[1]) * inv0[r2];
                    __stcs((float2*)(or0[r2] + c0), v);
                    v.x = __expf(accB[0]) * inv0[r2]; v.y = __expf(accB[1]) * inv0[r2];
                    __stcs((float2*)(or0[r2] + c0 + 8), v);
                    v.x = __expf(accA[2]) * inv1[r2]; v.y = __expf(accA[3]) * inv1[r2];
                    __stcs((float2*)(or1[r2] + c0), v);
                    v.x = __expf(accB[2]) * inv1[r2]; v.y = __expf(accB[3]) * inv1[r2];
                    __stcs((float2*)(or1[r2] + c0 + 8), v);
                } else {
                    v.x = (c0     <= grow0[r2]) ? __expf(accA[0]) * inv0[r2] : 0.f;
                    v.y = (c0 + 1 <= grow0[r2]) ? __expf(accA[1]) * inv0[r2] : 0.f;
                    __stcs((float2*)(or0[r2] + c0), v);
                    v.x = (c0 + 8 <= grow0[r2]) ? __expf(accB[0]) * inv0[r2] : 0.f;
                    v.y = (c0 + 9 <= grow0[r2]) ? __expf(accB[1]) * inv0[r2] : 0.f;
                    __stcs((float2*)(or0[r2] + c0 + 8), v);
                    v.x = (c0     <= grow1[r2]) ? __expf(accA[2]) * inv1[r2] : 0.f;
                    v.y = (c0 + 1 <= grow1[r2]) ? __expf(accA[3]) * inv1[r2] : 0.f;
                    __stcs((float2*)(or1[r2] + c0), v);
                    v.x = (c0 + 8 <= grow1[r2]) ? __expf(accB[2]) * inv1[r2] : 0.f;
                    v.y = (c0 + 9 <= grow1[r2]) ? __expf(accB[3]) * inv1[r2] : 0.f;
                    __stcs((float2*)(or1[r2] + c0 + 8), v);
                }
            }
        }
        __syncthreads();
        if (i + 3 < nm) issue_tile(sb, (i + 3) % 3, kb + ((size_t)(i + 3) << 14), tid, true);
        CP_COMMIT();
    }
}

extern "C" void kernel_launch(void* const* d_in, const int* in_sizes, int n_in,
                              void* d_out, int out_size)
{
    const float* q = (const float*)d_in[0];
    const float* k = (const float*)d_in[1];
    float* out = (float*)d_out;

    // merged prep: [0,768) q-frag prep, [768,2304) k tile prep
    prep_all<<<2304, 128>>>(q, k);

    cudaFuncSetAttribute(sdp_fused,
                         cudaFuncAttributeMaxDynamicSharedMemorySize, SMEM_BYTES);
    // z: per-bh interleave — even z = sum CTAs of bh=z/2, odd z = store CTAs
    sdp_fused<<<dim3(4, 16, 2 * NBH), 128, SMEM_BYTES>>>(out);
}

// round 16
// speedup vs baseline: 1.7467x; 1.1192x over previous
#include <cuda_runtime.h>
#include <cuda_bf16.h>
#include <cstdint>

// causal softmax(QK^T/sqrt(64)): q,k [48,2048,64] fp32 -> out [48,2048,2048] fp32
//
// prep_all (ONE launch, bid-split):
//   [0,768)    q -> bf16 hi/lo A-FRAGMENT-layout scratch; zero partials+flags
//   [768,2304) k -> bf16 hi/lo swizzled smem-image tile scratch
// sdp_fused: LAG-8 phase interleave over blockIdx.z in [0,96):
//   z<8: sum(bh=z). 8<=z<88: q=z-8; q even -> store(q/2), q odd -> sum(8+q/2).
//   z>=88: store(40 + z-88).
//   Store(b) trails sums(0..b+7) (>=512 CTAs = a full residency wave) -> ~zero
//   spin, while steady-state resident mix is ~50/50 sum/store (tensor-heavy
//   overlapped with write-heavy).
//   sum: MMA (1-split bf16 qb>=1 / 3-split qb==0) + exp -> partial row sums;
//        post flag (release); upper-triangle zero-fill (streaming stores).
//   store: prefetch K + A frags, spin (acquire) on flag, 3-split MMA, exp,
//        normalize, streaming stores (__stcs).
// Deadlock-free: producers have strictly lower dispatch positions; sums never wait.

#define TT 2048
#define NBH 48
#define LAG 8

__device__ __align__(16) char g_qf[(size_t)NBH * 16 * 32768];  // [bh][qb]: hi 16KB | lo 16KB
__device__ __align__(16) char g_ki[(size_t)NBH * 32 * 16384];  // [bh][t64]: hi 8KB | lo 8KB
__device__ float g_part[NBH * 16 * 4 * 128];                   // [bh][qb][chunk][row]
__device__ unsigned g_flag[NBH * 16];                          // completed chunks per (bh,qb)

#define SMEM_BYTES (3 * 16384)

__device__ __forceinline__ uint32_t smem_u32(const void* p) {
    uint32_t a;
    asm("{ .reg .u64 t; cvta.to.shared.u64 t, %1; cvt.u32.u64 %0, t; }" : "=r"(a) : "l"(p));
    return a;
}
__device__ __forceinline__ void ldsm_x4(uint32_t r[4], uint32_t addr) {
    asm volatile("ldmatrix.sync.aligned.m8n8.x4.shared.b16 {%0,%1,%2,%3}, [%4];"
        : "=r"(r[0]), "=r"(r[1]), "=r"(r[2]), "=r"(r[3]) : "r"(addr));
}
__device__ __forceinline__ void mma16816(float c[4], const uint32_t a[4], const uint32_t b[2]) {
    asm volatile("mma.sync.aligned.m16n8k16.row.col.f32.bf16.bf16.f32 "
        "{%0,%1,%2,%3}, {%4,%5,%6,%7}, {%8,%9}, {%0,%1,%2,%3};"
        : "+f"(c[0]), "+f"(c[1]), "+f"(c[2]), "+f"(c[3])
        : "r"(a[0]), "r"(a[1]), "r"(a[2]), "r"(a[3]), "r"(b[0]), "r"(b[1]));
}
#define CP_ASYNC16(sa, gp) \
    asm volatile("cp.async.cg.shared.global [%0], [%1], 16;" :: "r"(sa), "l"(gp))
#define CP_COMMIT() asm volatile("cp.async.commit_group;")
#define CP_WAIT2()  asm volatile("cp.async.wait_group 2;")

__device__ __forceinline__ void split2(float x, float y, uint32_t& h, uint32_t& l) {
    __nv_bfloat16 hx = __float2bfloat16(x);
    __nv_bfloat16 hy = __float2bfloat16(y);
    __nv_bfloat162 hv; hv.x = hx; hv.y = hy;
    __nv_bfloat162 lv;
    lv.x = __float2bfloat16(x - __bfloat162float(hx));
    lv.y = __float2bfloat16(y - __bfloat162float(hy));
    h = *reinterpret_cast<uint32_t*>(&hv);
    l = *reinterpret_cast<uint32_t*>(&lv);
}

// ---------------- prep_all: q-frag prep [0,768) | k tile prep [768,2304) ----------------
__global__ void __launch_bounds__(128)
prep_all(const float* __restrict__ qg, const float* __restrict__ kg)
{
    __shared__ __align__(16) char sm[32768];
    const int tid = threadIdx.x, w = tid >> 5, lane = tid & 31;
    int bid = (int)blockIdx.x;

    if (bid < 768) {
        const int qb = bid & 15, bh = bid >> 4;
        {
            const int base = ((bh << 4) + qb) << 9;
            #pragma unroll
            for (int j = 0; j < 4; j++) g_part[base + (j << 7) + tid] = 0.0f;
            if (tid == 0) g_flag[(bh << 4) + qb] = 0u;
        }

        const float* qptr = qg + ((size_t)bh * TT + (qb << 7)) * 64;
        #pragma unroll
        for (int i = 0; i < 8; i++) {
            const int idx = tid + (i << 7);
            const int r = idx >> 3, c = idx & 7;
            const float* p = qptr + r * 64 + (c << 3);
            float4 v0 = *(const float4*)p;
            float4 v1 = *(const float4*)(p + 4);
            v0.x *= 0.125f; v0.y *= 0.125f; v0.z *= 0.125f; v0.w *= 0.125f;
            v1.x *= 0.125f; v1.y *= 0.125f; v1.z *= 0.125f; v1.w *= 0.125f;
            uint4 h, l;
            split2(v0.x, v0.y, h.x, l.x);
            split2(v0.z, v0.w, h.y, l.y);
            split2(v1.x, v1.y, h.z, l.z);
            split2(v1.z, v1.w, h.w, l.w);
            const uint32_t off = (r << 7) + (((uint32_t)c ^ (r & 7)) << 4);
            *(uint4*)(sm + off) = h;
            *(uint4*)(sm + 16384 + off) = l;
        }
        __syncthreads();

        const uint32_t sb = smem_u32(sm);
        uint32_t ah[2][4][4], al[2][4][4];
        const int cpar = lane >> 4;
        #pragma unroll
        for (int r2 = 0; r2 < 2; r2++) {
            const int rA = (w << 5) + (r2 << 4) + (lane & 15);
            #pragma unroll
            for (int kc = 0; kc < 4; kc++) {
                const uint32_t off = (uint32_t)(rA << 7)
                                   + (((uint32_t)((kc << 1) + cpar) ^ (rA & 7)) << 4);
                ldsm_x4(ah[r2][kc], sb + off);
                ldsm_x4(al[r2][kc], sb + 16384 + off);
            }
        }
        char* dst = g_qf + ((size_t)((bh << 4) + qb) << 15);
        #pragma unroll
        for (int r2 = 0; r2 < 2; r2++) {
            const int g = (w << 1) + r2;
            #pragma unroll
            for (int kc = 0; kc < 4; kc++) {
                const uint32_t a = (uint32_t)(((((g << 2) + kc) << 5) + lane) << 4);
                *(uint4*)(dst + a) =
                    make_uint4(ah[r2][kc][0], ah[r2][kc][1], ah[r2][kc][2], ah[r2][kc][3]);
                *(uint4*)(dst + 16384 + a) =
                    make_uint4(al[r2][kc][0], al[r2][kc][1], al[r2][kc][2], al[r2][kc][3]);
            }
        }
        return;
    }

    // ---- k prep: 1536 CTAs x 512 chunks/CTA covers 786432 chunks ----
    bid -= 768;
    #pragma unroll
    for (int j = 0; j < 4; j++) {
        const int idx = (bid << 9) + (j << 7) + tid;
        const int kgr = idx >> 3;
        const int c   = idx & 7;
        const float* p = kg + (size_t)kgr * 64 + (c << 3);
        const float4 v0 = *(const float4*)p;
        const float4 v1 = *(const float4*)(p + 4);
        uint4 h, l;
        split2(v0.x, v0.y, h.x, l.x);
        split2(v0.z, v0.w, h.y, l.y);
        split2(v1.x, v1.y, h.z, l.z);
        split2(v1.z, v1.w, h.w, l.w);
        const uint32_t t64 = (uint32_t)kgr >> 6;
        const uint32_t row = (uint32_t)kgr & 63;
        const size_t off = ((size_t)t64 << 14) + row * 128 + (((uint32_t)c ^ (row & 7)) << 4);
        *(uint4*)(g_ki + off) = h;
        *(uint4*)(g_ki + off + 8192) = l;
    }
}

// ---------------- shared machinery ----------------
__device__ __forceinline__ void load_afrags(const char* src, int w, int lane, bool with_lo,
                                            uint32_t ah[2][4][4], uint32_t al[2][4][4])
{
    #pragma unroll
    for (int r2 = 0; r2 < 2; r2++) {
        const int g = (w << 1) + r2;
        #pragma unroll
        for (int kc = 0; kc < 4; kc++) {
            const uint32_t a = (uint32_t)(((((g << 2) + kc) << 5) + lane) << 4);
            const uint4 h = *(const uint4*)(src + a);
            ah[r2][kc][0] = h.x; ah[r2][kc][1] = h.y; ah[r2][kc][2] = h.z; ah[r2][kc][3] = h.w;
            if (with_lo) {
                const uint4 l = *(const uint4*)(src + 16384 + a);
                al[r2][kc][0] = l.x; al[r2][kc][1] = l.y; al[r2][kc][2] = l.z; al[r2][kc][3] = l.w;
            }
        }
    }
}

__device__ __forceinline__ void issue_tile(uint32_t sb, int stage, const char* src,
                                           int tid, bool with_lo)
{
    const uint32_t dst = sb + ((uint32_t)stage << 14) + ((uint32_t)tid << 4);
    const char* s = src + (tid << 4);
    #pragma unroll
    for (int i = 0; i < 4; i++)
        CP_ASYNC16(dst + (i << 11), s + (i << 11));
    if (with_lo) {
        #pragma unroll
        for (int i = 4; i < 8; i++)
            CP_ASYNC16(dst + (i << 11), s + (i << 11));
    }
}

__device__ __forceinline__ void mma_tile3(uint32_t nbase, const uint32_t bOff[4],
                                          const uint32_t ah[2][4][4], const uint32_t al[2][4][4],
                                          float a00[4], float a01[4], float a10[4], float a11[4])
{
    #pragma unroll
    for (int kc = 0; kc < 4; kc++) {
        uint32_t bhr[4], blr[4];
        ldsm_x4(bhr, nbase + bOff[kc]);
        ldsm_x4(blr, nbase + 8192 + bOff[kc]);
        mma16816(a00, ah[0][kc], &bhr[0]);
        mma16816(a01, ah[0][kc], &bhr[2]);
        mma16816(a10, ah[1][kc], &bhr[0]);
        mma16816(a11, ah[1][kc], &bhr[2]);
        mma16816(a00, ah[0][kc], &blr[0]);
        mma16816(a01, ah[0][kc], &blr[2]);
        mma16816(a10, ah[1][kc], &blr[0]);
        mma16816(a11, ah[1][kc], &blr[2]);
        mma16816(a00, al[0][kc], &bhr[0]);
        mma16816(a01, al[0][kc], &bhr[2]);
        mma16816(a10, al[1][kc], &bhr[0]);
        mma16816(a11, al[1][kc], &bhr[2]);
    }
}

__device__ __forceinline__ void mma_tile1(uint32_t nbase, const uint32_t bOff[4],
                                          const uint32_t ah[2][4][4],
                                          float a00[4], float a01[4], float a10[4], float a11[4])
{
    #pragma unroll
    for (int kc = 0; kc < 4; kc++) {
        uint32_t bhr[4];
        ldsm_x4(bhr, nbase + bOff[kc]);
        mma16816(a00, ah[0][kc], &bhr[0]);
        mma16816(a01, ah[0][kc], &bhr[2]);
        mma16816(a10, ah[1][kc], &bhr[0]);
        mma16816(a11, ah[1][kc], &bhr[2]);
    }
}

// ---------------- fused sum+store kernel (lag-8 interleaved phases) ----------------
__global__ void __launch_bounds__(128, 4)
sdp_fused(float* __restrict__ outg)
{
    extern __shared__ char smem[];
    const uint32_t sb = smem_u32(smem);
    const int tid = threadIdx.x, w = tid >> 5, lane = tid & 31;
    const int ch = blockIdx.x;
    const int qb = 15 - (int)blockIdx.y;

    // lag-8 phase decode
    int bh, is_store;
    {
        const int z = (int)blockIdx.z;              // [0, 96)
        if (z < LAG) { bh = z; is_store = 0; }
        else if (z < LAG + 2 * (NBH - LAG)) {
            const int q = z - LAG;
            if ((q & 1) == 0) { bh = q >> 1; is_store = 1; }
            else             { bh = LAG + (q >> 1); is_store = 0; }
        } else {
            bh = (NBH - LAG) + (z - (LAG + 2 * (NBH - LAG)));
            is_store = 1;
        }
    }

    const int t_lo = ch << 3;
    const int dlim = 2 * qb + 1;
    const int q0 = qb << 7;
    const int nchunks = (dlim >> 3) + 1;
    const int fidx = (bh << 4) + qb;
    float* outp = outg + (size_t)bh * TT * TT;

    if (is_store && t_lo > dlim) return;

    const bool has_mma = (t_lo <= dlim);
    const int t_hi = min(t_lo + 7, dlim);
    const int nm = has_mma ? (t_hi - t_lo + 1) : 0;
    const bool full = is_store || (qb == 0);

    uint32_t ah[2][4][4], al[2][4][4];
    const int rowB  = (lane & 7) + ((lane >> 4) << 3);
    const int cparB = (lane >> 3) & 1;
    uint32_t bOff[4];
    #pragma unroll
    for (int kc = 0; kc < 4; kc++)
        bOff[kc] = (uint32_t)(rowB << 7)
                 + (((uint32_t)((kc << 1) + cparB) ^ (rowB & 7)) << 4);
    const int cbase = (lane & 3) << 1;
    int lr[2], grow0[2], grow1[2];
    #pragma unroll
    for (int r2 = 0; r2 < 2; r2++) {
        lr[r2] = (w << 5) + (r2 << 4) + (lane >> 2);
        grow0[r2] = q0 + lr[r2];
        grow1[r2] = grow0[r2] + 8;
    }

    const char* kb = g_ki + ((size_t)(bh * 32 + t_lo) << 14);

    if (has_mma) {
        load_afrags(g_qf + ((size_t)fidx << 15), w, lane, full, ah, al);
        #pragma unroll
        for (int p = 0; p < 3; p++) {
            if (p < nm) issue_tile(sb, p, kb + ((size_t)p << 14), tid, full);
            CP_COMMIT();
        }
    }

    if (!is_store) {
        // =================== SUM PHASE ===================
        if (has_mma) {
            float s0[2] = {0.f, 0.f}, s1[2] = {0.f, 0.f};
            #pragma unroll 1
            for (int i = 0; i < nm; i++) {
                CP_WAIT2();
                __syncthreads();
                const uint32_t stg = sb + ((uint32_t)(i % 3) << 14);
                const int tg = t_lo + i;
                const bool msk = (tg >= 2 * qb);
                #pragma unroll 1
                for (int nfp = 0; nfp < 4; nfp++) {
                    float a00[4] = {0,0,0,0}, a01[4] = {0,0,0,0};
                    float a10[4] = {0,0,0,0}, a11[4] = {0,0,0,0};
                    const uint32_t nbase = stg + ((uint32_t)nfp << 11);
                    if (full) mma_tile3(nbase, bOff, ah, al, a00, a01, a10, a11);
                    else      mma_tile1(nbase, bOff, ah,     a00, a01, a10, a11);

                    const int c0 = (tg << 6) + (nfp << 4) + cbase;
                    #pragma unroll
                    for (int r2 = 0; r2 < 2; r2++) {
                        float* accA = r2 ? a10 : a00;
                        float* accB = r2 ? a11 : a01;
                        if (!msk) {
                            s0[r2] += __expf(accA[0]) + __expf(accA[1])
                                    + __expf(accB[0]) + __expf(accB[1]);
                            s1[r2] += __expf(accA[2]) + __expf(accA[3])
                                    + __expf(accB[2]) + __expf(accB[3]);
                        } else {
                            if (c0     <= grow0[r2]) s0[r2] += __expf(accA[0]);
                            if (c0 + 1 <= grow0[r2]) s0[r2] += __expf(accA[1]);
                            if (c0 + 8 <= grow0[r2]) s0[r2] += __expf(accB[0]);
                            if (c0 + 9 <= grow0[r2]) s0[r2] += __expf(accB[1]);
                            if (c0     <= grow1[r2]) s1[r2] += __expf(accA[2]);
                            if (c0 + 1 <= grow1[r2]) s1[r2] += __expf(accA[3]);
                            if (c0 + 8 <= grow1[r2]) s1[r2] += __expf(accB[2]);
                            if (c0 + 9 <= grow1[r2]) s1[r2] += __expf(accB[3]);
                        }
                    }
                }
                __syncthreads();
                if (i + 3 < nm) issue_tile(sb, (i + 3) % 3, kb + ((size_t)(i + 3) << 14), tid, full);
                CP_COMMIT();
            }

            #pragma unroll
            for (int r2 = 0; r2 < 2; r2++) {
                s0[r2] += __shfl_xor_sync(0xffffffffu, s0[r2], 1);
                s0[r2] += __shfl_xor_sync(0xffffffffu, s0[r2], 2);
                s1[r2] += __shfl_xor_sync(0xffffffffu, s1[r2], 1);
                s1[r2] += __shfl_xor_sync(0xffffffffu, s1[r2], 2);
            }
            if ((lane & 3) == 0) {
                float* pp = g_part + (size_t)(((fidx << 2) + ch) << 7);
                #pragma unroll
                for (int r2 = 0; r2 < 2; r2++) {
                    pp[lr[r2]]     = s0[r2];
                    pp[lr[r2] + 8] = s1[r2];
                }
            }
            __threadfence();
            __syncthreads();
            if (tid == 0) atomicAdd(&g_flag[fidx], 1u);
        }

        // zero-fill tiles of this chunk above the diagonal band (streaming stores)
        const int z_lo = max(t_lo, 2 * qb + 2);
        const float4 z4 = make_float4(0.f, 0.f, 0.f, 0.f);
        for (int tg = z_lo; tg <= t_lo + 7; tg++) {
            #pragma unroll
            for (int i = 0; i < 16; i++) {
                const int idx = tid + (i << 7);
                const int rr = idx >> 4, c4 = idx & 15;
                __stcs((float4*)(outp + (size_t)(q0 + rr) * TT + (tg << 6) + (c4 << 2)), z4);
            }
        }
        return;
    }

    // =================== STORE PHASE ===================
    if (tid == 0) {
        unsigned v;
        do {
            asm volatile("ld.acquire.gpu.global.b32 %0, [%1];"
                         : "=r"(v) : "l"(&g_flag[fidx]) : "memory");
            if ((int)v >= nchunks) break;
            __nanosleep(128);
        } while (true);
    }
    __syncthreads();

    float inv0[2], inv1[2];
    float* or0[2]; float* or1[2];
    const float* pp = g_part + ((size_t)fidx << 9);
    #pragma unroll
    for (int r2 = 0; r2 < 2; r2++) {
        const int ra = lr[r2], rb = lr[r2] + 8;
        inv0[r2] = 1.0f / (pp[ra] + pp[128 + ra] + pp[256 + ra] + pp[384 + ra]);
        inv1[r2] = 1.0f / (pp[rb] + pp[128 + rb] + pp[256 + rb] + pp[384 + rb]);
        or0[r2] = outp + (size_t)grow0[r2] * TT;
        or1[r2] = outp + (size_t)grow1[r2] * TT;
    }

    #pragma unroll 1
    for (int i = 0; i < nm; i++) {
        CP_WAIT2();
        __syncthreads();
        const uint32_t stg = sb + ((uint32_t)(i % 3) << 14);
        const int tg = t_lo + i;
        const bool msk = (tg >= 2 * qb);
        #pragma unroll 1
        for (int nfp = 0; nfp < 4; nfp++) {
            float a00[4] = {0,0,0,0}, a01[4] = {0,0,0,0};
            float a10[4] = {0,0,0,0}, a11[4] = {0,0,0,0};
            const uint32_t nbase = stg + ((uint32_t)nfp << 11);
            mma_tile3(nbase, bOff, ah, al, a00, a01, a10, a11);

            const int c0 = (tg << 6) + (nfp << 4) + cbase;
            #pragma unroll
            for (int r2 = 0; r2 < 2; r2++) {
                float* accA = r2 ? a10 : a00;
                float* accB = r2 ? a11 : a01;
                float2 v;
                if (!msk) {
                    v.x = __expf(accA[0]) * inv0[r2]; v.y = __expf(accA[1]) * inv0[r2];
                    __stcs((float2*)(or0[r2] + c0), v);
                    v.x = __expf(accB[0]) * inv0[r2]; v.y = __expf(accB[1]) * inv0[r2];
                    __stcs((float2*)(or0[r2] + c0 + 8), v);
                    v.x = __expf(accA[2]) * inv1[r2]; v.y = __expf(accA[3]) * inv1[r2];
                    __stcs((float2*)(or1[r2] + c0), v);
                    v.x = __expf(accB[2]) * inv1[r2]; v.y = __expf(accB[3]) * inv1[r2];
                    __stcs((float2*)(or1[r2] + c0 + 8), v);
                } else {
                    v.x = (c0     <= grow0[r2]) ? __expf(accA[0]) * inv0[r2] : 0.f;
                    v.y = (c0 + 1 <= grow0[r2]) ? __expf(accA[1]) * inv0[r2] : 0.f;
                    __stcs((float2*)(or0[r2] + c0), v);
                    v.x = (c0 + 8 <= grow0[r2]) ? __expf(accB[0]) * inv0[r2] : 0.f;
                    v.y = (c0 + 9 <= grow0[r2]) ? __expf(accB[1]) * inv0[r2] : 0.f;
                    __stcs((float2*)(or0[r2] + c0 + 8), v);
                    v.x = (c0     <= grow1[r2]) ? __expf(accA[2]) * inv1[r2] : 0.f;
                    v.y = (c0 + 1 <= grow1[r2]) ? __expf(accA[3]) * inv1[r2] : 0.f;
                    __stcs((float2*)(or1[r2] + c0), v);
                    v.x = (c0 + 8 <= grow1[r2]) ? __expf(accB[2]) * inv1[r2] : 0.f;
                    v.y = (c0 + 9 <= grow1[r2]) ? __expf(accB[3]) * inv1[r2] : 0.f;
                    __stcs((float2*)(or1[r2] + c0 + 8), v);
                }
            }
        }
        __syncthreads();
        if (i + 3 < nm) issue_tile(sb, (i + 3) % 3, kb + ((size_t)(i + 3) << 14), tid, true);
        CP_COMMIT();
    }
}

extern "C" void kernel_launch(void* const* d_in, const int* in_sizes, int n_in,
                              void* d_out, int out_size)
{
    const float* q = (const float*)d_in[0];
    const float* k = (const float*)d_in[1];
    float* out = (float*)d_out;

    // merged prep: [0,768) q-frag prep, [768,2304) k tile prep
    prep_all<<<2304, 128>>>(q, k);

    cudaFuncSetAttribute(sdp_fused,
                         cudaFuncAttributeMaxDynamicSharedMemorySize, SMEM_BYTES);
    // z in [0,96): lag-8 interleave of sum/store groups (see decode in kernel)
    sdp_fused<<<dim3(4, 16, 2 * NBH), 128, SMEM_BYTES>>>(out);
}